// round 15
// baseline (speedup 1.0000x reference)
#include <cuda_runtime.h>
#include <cuda_fp16.h>
#include <cstdint>
#include <cstddef>

// ---------------- problem constants ----------------
#define BB 4
#define TT 2048
#define DD 768
#define HH 12
#define HD 64
#define WIN 128
#define QT 64
#define NKM 192

// ---------------- GEMM tiling (fp16, 64x128 CTA tile) ----------------
#define MTT 64
#define NTT 128
#define KC 64
#define KDIM 768
#define NCHUNK (KDIM / KC)     // 12
#define GEMM_THREADS 256
#define STRH 72                // row stride in halfs (144B rows, word 36 ≡ 4 mod 32)
#define TILE_A_H (MTT * STRH)  // 4608 halfs
#define TILE_B_H (NTT * STRH)  // 9216 halfs
#define STAGE_H  (TILE_A_H + TILE_B_H)
#define GEMM_SMEM (2 * STAGE_H * 2)    // 55296 B -> 3 CTAs/SM

// ---------------- attention smem ----------------
#define ATHR 128               // 4 warps
#define SQH 72
#define ATT_SMEM ((QT * SQH + NKM * SQH + NKM * SQH) * 2)   // 64512 B -> 3 CTAs/SM

// ---------------- fused preprocessing grid sections ----------------
#define CONV_N2    ((BB * TT * DD) / 2)
#define CONV_BLKS  (CONV_N2 / 256)               // 12288
#define T1_BX      (3 * DD / 32)                 // 72
#define T1_BLKS    (T1_BX * (DD / 32))           // 1728
#define T2_BX      (DD / 32)                     // 24
#define T2_BLKS    (T2_BX * (DD / 32))           // 576
#define PRE_BLKS   (CONV_BLKS + T1_BLKS + T2_BLKS)

// ---------------- device scratch ----------------
__device__ __align__(128) __half g_x16 [(size_t)BB * TT * DD];
__device__ __align__(128) __half g_qkv [(size_t)BB * TT * 3 * DD];
__device__ __align__(128) __half g_att [(size_t)BB * TT * DD];
__device__ __align__(128) __half g_wqkvT[(size_t)3 * DD * DD];
__device__ __align__(128) __half g_woutT[(size_t)DD * DD];

// ---------------- helpers ----------------
__device__ __forceinline__ uint32_t smem_u32(const void* p) {
    uint32_t a;
    asm("{ .reg .u64 t; cvta.to.shared.u64 t, %1; cvt.u32.u64 %0, t; }" : "=r"(a) : "l"(p));
    return a;
}
__device__ __forceinline__ void cpa16(uint32_t s, const void* g) {
    asm volatile("cp.async.cg.shared.global [%0], [%1], 16;" :: "r"(s), "l"(g));
}
__device__ __forceinline__ void ldsm_x4(uint32_t* r, uint32_t addr) {
    asm volatile("ldmatrix.sync.aligned.m8n8.x4.shared.b16 {%0,%1,%2,%3}, [%4];"
        : "=r"(r[0]), "=r"(r[1]), "=r"(r[2]), "=r"(r[3]) : "r"(addr));
}
__device__ __forceinline__ void ldsm_x4_t(uint32_t* r, uint32_t addr) {
    asm volatile("ldmatrix.sync.aligned.m8n8.x4.trans.shared.b16 {%0,%1,%2,%3}, [%4];"
        : "=r"(r[0]), "=r"(r[1]), "=r"(r[2]), "=r"(r[3]) : "r"(addr));
}
__device__ __forceinline__ void mma_f16_16x8x16(float* d, const uint32_t* a, const uint32_t* b) {
    asm volatile(
        "mma.sync.aligned.m16n8k16.row.col.f32.f16.f16.f32 "
        "{%0,%1,%2,%3}, {%4,%5,%6,%7}, {%8,%9}, {%0,%1,%2,%3};"
        : "+f"(d[0]), "+f"(d[1]), "+f"(d[2]), "+f"(d[3])
        : "r"(a[0]), "r"(a[1]), "r"(a[2]), "r"(a[3]), "r"(b[0]), "r"(b[1]));
}
__device__ __forceinline__ uint32_t pack_h2(float a, float b) {
    __half2 h = __floats2half2_rn(a, b);
    return *reinterpret_cast<uint32_t*>(&h);
}

// ---------------------------------------------------------------------------
// Fused preprocessing: x f32->f16 | Wqkv transpose->f16 | Wout transpose->f16
// ---------------------------------------------------------------------------
__global__ void __launch_bounds__(256) pre_k(const float* __restrict__ x,
                                             __half* __restrict__ x16,
                                             const float* __restrict__ Wqkv,
                                             __half* __restrict__ wqkvT,
                                             const float* __restrict__ Wout,
                                             __half* __restrict__ woutT) {
    const int bid = blockIdx.x;
    const int tid = threadIdx.x;
    if (bid < CONV_BLKS) {
        int i = bid * 256 + tid;
        float2 v = reinterpret_cast<const float2*>(x)[i];
        reinterpret_cast<__half2*>(x16)[i] = __floats2half2_rn(v.x, v.y);
        return;
    }
    __shared__ float t[32][33];
    const int xx = tid & 31, yy = tid >> 5;
    const float* src;
    __half* dst;
    int R, C, c0, r0;
    if (bid < CONV_BLKS + T1_BLKS) {
        int b = bid - CONV_BLKS;
        src = Wqkv; dst = wqkvT; R = DD; C = 3 * DD;
        c0 = (b % T1_BX) * 32; r0 = (b / T1_BX) * 32;
    } else {
        int b = bid - CONV_BLKS - T1_BLKS;
        src = Wout; dst = woutT; R = DD; C = DD;
        c0 = (b % T2_BX) * 32; r0 = (b / T2_BX) * 32;
    }
#pragma unroll
    for (int dy = 0; dy < 32; dy += 8)
        t[yy + dy][xx] = src[(size_t)(r0 + yy + dy) * C + c0 + xx];
    __syncthreads();
#pragma unroll
    for (int dy = 0; dy < 32; dy += 8)
        dst[(size_t)(c0 + yy + dy) * R + r0 + xx] = __float2half_rn(t[xx][yy + dy]);
}

// ---------------------------------------------------------------------------
// fp16 mma.sync GEMM, 64x128 CTA tile, 32x32 warp tile, 3 CTAs/SM.
// ---------------------------------------------------------------------------
__global__ void __launch_bounds__(GEMM_THREADS, 3) gemm_f16(const __half* __restrict__ A,
                                                            const __half* __restrict__ Bt,
                                                            void* __restrict__ Cv,
                                                            int N, int out_half) {
    extern __shared__ __half smh[];
    const uint32_t sAu[2] = { smem_u32(smh),            smem_u32(smh + STAGE_H) };
    const uint32_t sBu[2] = { sAu[0] + TILE_A_H * 2u,   sAu[1] + TILE_A_H * 2u };

    const int tid = threadIdx.x;
    const int wid = tid >> 5, lane = tid & 31;
    const int gid = lane >> 2, tg = lane & 3;
    const int wm = (wid & 1) * 32;      // 2 M-warps
    const int wn = (wid >> 1) * 32;     // 4 N-warps
    const int bm = blockIdx.y * MTT;
    const int bn = blockIdx.x * NTT;

    const uint32_t aoff = (uint32_t)((wm + (lane & 7) + ((lane >> 3) & 1) * 8) * STRH
                                     + (lane >> 4) * 8) * 2u;
    const uint32_t boff = (uint32_t)((wn + (lane & 7) + ((lane >> 4) & 1) * 8) * STRH
                                     + ((lane >> 3) & 1) * 8) * 2u;
    const uint32_t AMI = 16 * STRH * 2;
    const uint32_t BNI = 16 * STRH * 2;

    // Loaders: A tile 64 rows (2 slots/thread), B tile 128 rows (4 slots/thread)
    int arow[2], ac8[2], brow[4], bc8[4];
    const __half *gA[2], *gB[4];
#pragma unroll
    for (int i = 0; i < 2; i++) {
        int f = tid + i * 256;
        arow[i] = f >> 3; ac8[i] = f & 7;
        gA[i] = A + (size_t)(bm + arow[i]) * KDIM + ac8[i] * 8;
    }
#pragma unroll
    for (int i = 0; i < 4; i++) {
        int f = tid + i * 256;
        brow[i] = f >> 3; bc8[i] = f & 7;
        gB[i] = Bt + (size_t)(bn + brow[i]) * KDIM + bc8[i] * 8;
    }

    auto load_chunk = [&](int kc, int s) {
        const int ko = kc * KC;
#pragma unroll
        for (int i = 0; i < 2; i++)
            cpa16(sAu[s] + (uint32_t)(arow[i] * STRH + ac8[i] * 8) * 2u, gA[i] + ko);
#pragma unroll
        for (int i = 0; i < 4; i++)
            cpa16(sBu[s] + (uint32_t)(brow[i] * STRH + bc8[i] * 8) * 2u, gB[i] + ko);
        asm volatile("cp.async.commit_group;" ::: "memory");
    };

    float acc[2][4][4];
#pragma unroll
    for (int mi = 0; mi < 2; mi++)
#pragma unroll
        for (int ni = 0; ni < 4; ni++)
#pragma unroll
            for (int q = 0; q < 4; q++) acc[mi][ni][q] = 0.f;

    load_chunk(0, 0);

    for (int c = 0; c < NCHUNK; ++c) {
        const int s = c & 1;
        if (c + 1 < NCHUNK) {
            load_chunk(c + 1, s ^ 1);
            asm volatile("cp.async.wait_group 1;" ::: "memory");
        } else {
            asm volatile("cp.async.wait_group 0;" ::: "memory");
        }
        __syncthreads();

        const uint32_t abase = sAu[s] + aoff;
        const uint32_t bbase = sBu[s] + boff;
#pragma unroll
        for (int k16 = 0; k16 < 4; k16++) {
            uint32_t af[2][4], bq[2][4];
#pragma unroll
            for (int mi = 0; mi < 2; mi++)
                ldsm_x4(af[mi], abase + mi * AMI + k16 * 32);
#pragma unroll
            for (int nip = 0; nip < 2; nip++)
                ldsm_x4(bq[nip], bbase + nip * BNI + k16 * 32);
#pragma unroll
            for (int mi = 0; mi < 2; mi++)
#pragma unroll
                for (int ni = 0; ni < 4; ni++)
                    mma_f16_16x8x16(acc[mi][ni], af[mi], &bq[ni >> 1][(ni & 1) * 2]);
        }
        __syncthreads();
    }

#pragma unroll
    for (int mi = 0; mi < 2; mi++) {
        const int r0 = bm + wm + mi * 16 + gid;
#pragma unroll
        for (int ni = 0; ni < 4; ni++) {
            const int c0 = bn + wn + ni * 8 + tg * 2;
            if (out_half) {
                __half* Ch = (__half*)Cv;
                *reinterpret_cast<__half2*>(&Ch[(size_t)r0 * N + c0]) =
                    __floats2half2_rn(acc[mi][ni][0], acc[mi][ni][1]);
                *reinterpret_cast<__half2*>(&Ch[(size_t)(r0 + 8) * N + c0]) =
                    __floats2half2_rn(acc[mi][ni][2], acc[mi][ni][3]);
            } else {
                float* Cf = (float*)Cv;
                *reinterpret_cast<float2*>(&Cf[(size_t)r0 * N + c0]) =
                    make_float2(acc[mi][ni][0], acc[mi][ni][1]);
                *reinterpret_cast<float2*>(&Cf[(size_t)(r0 + 8) * N + c0]) =
                    make_float2(acc[mi][ni][2], acc[mi][ni][3]);
            }
        }
    }
}

// ---------------------------------------------------------------------------
// FA2-style attention (unchanged from R14 passing kernel).
// ---------------------------------------------------------------------------
__global__ void __launch_bounds__(ATHR, 3) attn_mma(const __half* __restrict__ qkv,
                                                    __half* __restrict__ att) {
    const int q0 = blockIdx.x * QT;
    const int h  = blockIdx.y;
    const int b  = blockIdx.z;
    const int tid = threadIdx.x;
    const int wid = tid >> 5, lane = tid & 31;
    const int gid = lane >> 2, tg = lane & 3;
    const int mrow = wid * 16;

    extern __shared__ __half smh[];
    __half* sQ = smh;
    __half* sK = sQ + QT  * SQH;
    __half* sV = sK + NKM * SQH;

    const int kstart = max(0, q0 - WIN);
    const int nk     = q0 + QT - kstart;
    const int hq     = h * HD;
    const size_t rowbase = (size_t)(b * TT) * (3 * DD);

    for (int idx = tid; idx < QT * (HD / 8); idx += ATHR) {
        int q = idx >> 3, d8 = (idx & 7) * 8;
        uint4 v = *reinterpret_cast<const uint4*>(
            &qkv[rowbase + (size_t)(q0 + q) * (3 * DD) + hq + d8]);
        *reinterpret_cast<uint4*>(&sQ[q * SQH + d8]) = v;
    }
    for (int idx = tid; idx < nk * (HD / 8); idx += ATHR) {
        int kk = idx >> 3, d8 = (idx & 7) * 8;
        uint4 v = *reinterpret_cast<const uint4*>(
            &qkv[rowbase + (size_t)(kstart + kk) * (3 * DD) + DD + hq + d8]);
        *reinterpret_cast<uint4*>(&sK[kk * SQH + d8]) = v;
        uint4 w = *reinterpret_cast<const uint4*>(
            &qkv[rowbase + (size_t)(kstart + kk) * (3 * DD) + 2 * DD + hq + d8]);
        *reinterpret_cast<uint4*>(&sV[kk * SQH + d8]) = w;
    }
    for (int idx = nk * (HD / 8) + tid; idx < NKM * (HD / 8); idx += ATHR) {
        int kk = idx >> 3, d8 = (idx & 7) * 8;
        *reinterpret_cast<uint4*>(&sV[kk * SQH + d8]) = make_uint4(0u, 0u, 0u, 0u);
    }
    __syncthreads();

    const uint32_t uQ = smem_u32(sQ);
    const uint32_t uK = smem_u32(sK);
    const uint32_t uV = smem_u32(sV);

    float accS[24][4];
#pragma unroll
    for (int ni = 0; ni < 24; ni++)
#pragma unroll
        for (int q = 0; q < 4; q++) accS[ni][q] = 0.f;

    {
        const uint32_t aoff = uQ + (uint32_t)((mrow + (lane & 7) + ((lane >> 3) & 1) * 8) * SQH
                                              + (lane >> 4) * 8) * 2u;
        const uint32_t boff = uK + (uint32_t)(((lane & 7) + ((lane >> 4) & 1) * 8) * SQH
                                              + ((lane >> 3) & 1) * 8) * 2u;
#pragma unroll
        for (int k16 = 0; k16 < 4; k16++) {
            uint32_t af[4];
            ldsm_x4(af, aoff + k16 * 32);
#pragma unroll
            for (int nip = 0; nip < 12; nip++) {
                uint32_t bq[4];
                ldsm_x4(bq, boff + nip * (16 * SQH * 2) + k16 * 32);
                mma_f16_16x8x16(accS[nip * 2],     af, &bq[0]);
                mma_f16_16x8x16(accS[nip * 2 + 1], af, &bq[2]);
            }
        }
    }

    const int i0 = q0 + mrow + gid, i1 = i0 + 8;
    const float scale = 0.125f;
#pragma unroll
    for (int ni = 0; ni < 24; ni++) {
        const int j0 = kstart + ni * 8 + 2 * tg, j1 = j0 + 1;
        accS[ni][0] = (j0 <= i0 && j0 >= i0 - WIN) ? accS[ni][0] * scale : -1e30f;
        accS[ni][1] = (j1 <= i0 && j1 >= i0 - WIN) ? accS[ni][1] * scale : -1e30f;
        accS[ni][2] = (j0 <= i1 && j0 >= i1 - WIN) ? accS[ni][2] * scale : -1e30f;
        accS[ni][3] = (j1 <= i1 && j1 >= i1 - WIN) ? accS[ni][3] * scale : -1e30f;
    }

    float m0 = -1e30f, m1 = -1e30f;
#pragma unroll
    for (int ni = 0; ni < 24; ni++) {
        m0 = fmaxf(m0, fmaxf(accS[ni][0], accS[ni][1]));
        m1 = fmaxf(m1, fmaxf(accS[ni][2], accS[ni][3]));
    }
    m0 = fmaxf(m0, __shfl_xor_sync(0xffffffffu, m0, 1));
    m0 = fmaxf(m0, __shfl_xor_sync(0xffffffffu, m0, 2));
    m1 = fmaxf(m1, __shfl_xor_sync(0xffffffffu, m1, 1));
    m1 = fmaxf(m1, __shfl_xor_sync(0xffffffffu, m1, 2));

    float s0 = 0.f, s1 = 0.f;
#pragma unroll
    for (int ni = 0; ni < 24; ni++) {
        accS[ni][0] = __expf(accS[ni][0] - m0);
        accS[ni][1] = __expf(accS[ni][1] - m0);
        accS[ni][2] = __expf(accS[ni][2] - m1);
        accS[ni][3] = __expf(accS[ni][3] - m1);
        s0 += accS[ni][0] + accS[ni][1];
        s1 += accS[ni][2] + accS[ni][3];
    }
    s0 += __shfl_xor_sync(0xffffffffu, s0, 1);
    s0 += __shfl_xor_sync(0xffffffffu, s0, 2);
    s1 += __shfl_xor_sync(0xffffffffu, s1, 1);
    s1 += __shfl_xor_sync(0xffffffffu, s1, 2);
    const float inv0 = 1.f / s0, inv1 = 1.f / s1;

    uint32_t pf[24], pg[24];
#pragma unroll
    for (int ni = 0; ni < 24; ni++) {
        pf[ni] = pack_h2(accS[ni][0] * inv0, accS[ni][1] * inv0);
        pg[ni] = pack_h2(accS[ni][2] * inv1, accS[ni][3] * inv1);
    }

    float accO[8][4];
#pragma unroll
    for (int ni = 0; ni < 8; ni++)
#pragma unroll
        for (int q = 0; q < 4; q++) accO[ni][q] = 0.f;

    {
        const uint32_t vbase = uV + (uint32_t)(((lane & 7) + ((lane >> 3) & 1) * 8) * SQH
                                               + ((lane >> 4) & 1) * 8) * 2u;
#pragma unroll
        for (int k16 = 0; k16 < 12; k16++) {
            uint32_t af[4] = { pf[2 * k16], pg[2 * k16], pf[2 * k16 + 1], pg[2 * k16 + 1] };
#pragma unroll
            for (int dp = 0; dp < 4; dp++) {
                uint32_t bq[4];
                ldsm_x4_t(bq, vbase + (uint32_t)(k16 * 16 * SQH + dp * 16) * 2u);
                mma_f16_16x8x16(accO[dp * 2],     af, &bq[0]);
                mma_f16_16x8x16(accO[dp * 2 + 1], af, &bq[2]);
            }
        }
    }

#pragma unroll
    for (int ni = 0; ni < 8; ni++) {
        const int dc = ni * 8 + 2 * tg;
        const int r  = mrow + gid;
        *reinterpret_cast<__half2*>(&att[(size_t)(b * TT + q0 + r) * DD + hq + dc]) =
            __floats2half2_rn(accO[ni][0], accO[ni][1]);
        *reinterpret_cast<__half2*>(&att[(size_t)(b * TT + q0 + r + 8) * DD + hq + dc]) =
            __floats2half2_rn(accO[ni][2], accO[ni][3]);
    }
}

// ---------------------------------------------------------------------------
extern "C" void kernel_launch(void* const* d_in, const int* in_sizes, int n_in,
                              void* d_out, int out_size) {
    const float* x    = (const float*)d_in[0];
    const float* Wqkv = (const float*)d_in[1];
    const float* Wout = (const float*)d_in[2];
    float* out = (float*)d_out;

    __half *x16, *qkv, *att, *wqkvT, *woutT;
    cudaGetSymbolAddress((void**)&x16, g_x16);
    cudaGetSymbolAddress((void**)&qkv, g_qkv);
    cudaGetSymbolAddress((void**)&att, g_att);
    cudaGetSymbolAddress((void**)&wqkvT, g_wqkvT);
    cudaGetSymbolAddress((void**)&woutT, g_woutT);

    cudaFuncSetAttribute(attn_mma, cudaFuncAttributeMaxDynamicSharedMemorySize, ATT_SMEM);
    cudaFuncSetAttribute(gemm_f16, cudaFuncAttributeMaxDynamicSharedMemorySize, GEMM_SMEM);

    const int M = BB * TT;   // 8192

    // 0) fused preprocessing
    pre_k<<<PRE_BLKS, 256>>>(x, x16, Wqkv, wqkvT, Wout, woutT);

    // 1) QKV projection: grid (18, 128)
    gemm_f16<<<dim3(3 * DD / NTT, M / MTT), GEMM_THREADS, GEMM_SMEM>>>(x16, wqkvT, qkv, 3 * DD, 1);

    // 2) attention
    attn_mma<<<dim3(TT / QT, HH, BB), ATHR, ATT_SMEM>>>(qkv, att);

    // 3) output projection: grid (6, 128)
    gemm_f16<<<dim3(DD / NTT, M / MTT), GEMM_THREADS, GEMM_SMEM>>>(att, woutT, out, DD, 0);
}

// round 16
// speedup vs baseline: 1.1015x; 1.1015x over previous
#include <cuda_runtime.h>
#include <cuda_fp16.h>
#include <cstdint>
#include <cstddef>

// ---------------- problem constants ----------------
#define BB 4
#define TT 2048
#define DD 768
#define HH 12
#define HD 64
#define WIN 128
#define QT 64
#define NKM 192

// ---------------- GEMM tiling (fp16, 128x128 — R14 proven config) ----------------
#define MT 128
#define NT 128
#define KC 64
#define KDIM 768
#define NCHUNK (KDIM / KC)
#define GEMM_THREADS 256
#define STRH 72
#define TILE_H (128 * STRH)
#define GEMM_SMEM (2 * 2 * TILE_H * 2)   // 73728 B -> 2 CTAs/SM

// ---------------- attention smem ----------------
#define ATHR 128               // 4 warps
#define SQH 72
#define ATT_SMEM ((QT * SQH + NKM * SQH + NKM * SQH) * 2)   // 64512 B -> 3 CTAs/SM

// ---------------- fused preprocessing grid sections ----------------
#define CONV_N2    ((BB * TT * DD) / 2)
#define CONV_BLKS  (CONV_N2 / 256)               // 12288
#define T1_BX      (3 * DD / 32)                 // 72
#define T1_BLKS    (T1_BX * (DD / 32))           // 1728
#define T2_BX      (DD / 32)                     // 24
#define T2_BLKS    (T2_BX * (DD / 32))           // 576
#define PRE_BLKS   (CONV_BLKS + T1_BLKS + T2_BLKS)

// ---------------- device scratch ----------------
__device__ __align__(128) __half g_x16 [(size_t)BB * TT * DD];
__device__ __align__(128) __half g_qkv [(size_t)BB * TT * 3 * DD];
__device__ __align__(128) __half g_att [(size_t)BB * TT * DD];
__device__ __align__(128) __half g_wqkvT[(size_t)3 * DD * DD];
__device__ __align__(128) __half g_woutT[(size_t)DD * DD];

// ---------------- helpers ----------------
__device__ __forceinline__ uint32_t smem_u32(const void* p) {
    uint32_t a;
    asm("{ .reg .u64 t; cvta.to.shared.u64 t, %1; cvt.u32.u64 %0, t; }" : "=r"(a) : "l"(p));
    return a;
}
__device__ __forceinline__ void cpa16(uint32_t s, const void* g) {
    asm volatile("cp.async.cg.shared.global [%0], [%1], 16;" :: "r"(s), "l"(g));
}
__device__ __forceinline__ void ldsm_x4(uint32_t* r, uint32_t addr) {
    asm volatile("ldmatrix.sync.aligned.m8n8.x4.shared.b16 {%0,%1,%2,%3}, [%4];"
        : "=r"(r[0]), "=r"(r[1]), "=r"(r[2]), "=r"(r[3]) : "r"(addr));
}
__device__ __forceinline__ void ldsm_x4_t(uint32_t* r, uint32_t addr) {
    asm volatile("ldmatrix.sync.aligned.m8n8.x4.trans.shared.b16 {%0,%1,%2,%3}, [%4];"
        : "=r"(r[0]), "=r"(r[1]), "=r"(r[2]), "=r"(r[3]) : "r"(addr));
}
__device__ __forceinline__ void mma_f16_16x8x16(float* d, const uint32_t* a, const uint32_t* b) {
    asm volatile(
        "mma.sync.aligned.m16n8k16.row.col.f32.f16.f16.f32 "
        "{%0,%1,%2,%3}, {%4,%5,%6,%7}, {%8,%9}, {%0,%1,%2,%3};"
        : "+f"(d[0]), "+f"(d[1]), "+f"(d[2]), "+f"(d[3])
        : "r"(a[0]), "r"(a[1]), "r"(a[2]), "r"(a[3]), "r"(b[0]), "r"(b[1]));
}
__device__ __forceinline__ uint32_t pack_h2(float a, float b) {
    __half2 h = __floats2half2_rn(a, b);
    return *reinterpret_cast<uint32_t*>(&h);
}

// ---------------------------------------------------------------------------
// Fused preprocessing: x f32->f16 | Wqkv transpose->f16 | Wout transpose->f16
// ---------------------------------------------------------------------------
__global__ void __launch_bounds__(256) pre_k(const float* __restrict__ x,
                                             __half* __restrict__ x16,
                                             const float* __restrict__ Wqkv,
                                             __half* __restrict__ wqkvT,
                                             const float* __restrict__ Wout,
                                             __half* __restrict__ woutT) {
    const int bid = blockIdx.x;
    const int tid = threadIdx.x;
    if (bid < CONV_BLKS) {
        int i = bid * 256 + tid;
        float2 v = reinterpret_cast<const float2*>(x)[i];
        reinterpret_cast<__half2*>(x16)[i] = __floats2half2_rn(v.x, v.y);
        return;
    }
    __shared__ float t[32][33];
    const int xx = tid & 31, yy = tid >> 5;
    const float* src;
    __half* dst;
    int R, C, c0, r0;
    if (bid < CONV_BLKS + T1_BLKS) {
        int b = bid - CONV_BLKS;
        src = Wqkv; dst = wqkvT; R = DD; C = 3 * DD;
        c0 = (b % T1_BX) * 32; r0 = (b / T1_BX) * 32;
    } else {
        int b = bid - CONV_BLKS - T1_BLKS;
        src = Wout; dst = woutT; R = DD; C = DD;
        c0 = (b % T2_BX) * 32; r0 = (b / T2_BX) * 32;
    }
#pragma unroll
    for (int dy = 0; dy < 32; dy += 8)
        t[yy + dy][xx] = src[(size_t)(r0 + yy + dy) * C + c0 + xx];
    __syncthreads();
#pragma unroll
    for (int dy = 0; dy < 32; dy += 8)
        dst[(size_t)(c0 + yy + dy) * R + r0 + xx] = __float2half_rn(t[xx][yy + dy]);
}

// ---------------------------------------------------------------------------
// fp16 mma.sync GEMM with ldmatrix fragment loads (R14 proven config).
// ---------------------------------------------------------------------------
__global__ void __launch_bounds__(GEMM_THREADS, 2) gemm_f16(const __half* __restrict__ A,
                                                            const __half* __restrict__ Bt,
                                                            void* __restrict__ Cv,
                                                            int N, int out_half) {
    extern __shared__ __half smh[];
    const uint32_t sAu[2] = { smem_u32(smh),          smem_u32(smh + 2 * TILE_H) };
    const uint32_t sBu[2] = { smem_u32(smh + TILE_H), smem_u32(smh + 3 * TILE_H) };

    const int tid = threadIdx.x;
    const int wid = tid >> 5, lane = tid & 31;
    const int gid = lane >> 2, tg = lane & 3;
    const int wm = (wid & 1) * 64;
    const int wn = (wid >> 1) * 32;
    const int bm = blockIdx.y * MT;
    const int bn = blockIdx.x * NT;

    const uint32_t aoff = (uint32_t)((wm + (lane & 7) + ((lane >> 3) & 1) * 8) * STRH
                                     + (lane >> 4) * 8) * 2u;
    const uint32_t boff = (uint32_t)((wn + (lane & 7) + ((lane >> 4) & 1) * 8) * STRH
                                     + ((lane >> 3) & 1) * 8) * 2u;
    const uint32_t AMI = 16 * STRH * 2;
    const uint32_t BNI = 16 * STRH * 2;

    int lrow[4], lc8[4];
    const __half *gA[4], *gB[4];
#pragma unroll
    for (int i = 0; i < 4; i++) {
        int f = tid + i * 256;
        lrow[i] = f >> 3;
        lc8[i]  = f & 7;
        gA[i] = A  + (size_t)(bm + lrow[i]) * KDIM + lc8[i] * 8;
        gB[i] = Bt + (size_t)(bn + lrow[i]) * KDIM + lc8[i] * 8;
    }

    auto load_chunk = [&](int kc, int s) {
        const int ko = kc * KC;
#pragma unroll
        for (int i = 0; i < 4; i++) {
            uint32_t off = (uint32_t)(lrow[i] * STRH + lc8[i] * 8) * 2u;
            cpa16(sAu[s] + off, gA[i] + ko);
            cpa16(sBu[s] + off, gB[i] + ko);
        }
        asm volatile("cp.async.commit_group;" ::: "memory");
    };

    float acc[4][4][4];
#pragma unroll
    for (int mi = 0; mi < 4; mi++)
#pragma unroll
        for (int ni = 0; ni < 4; ni++)
#pragma unroll
            for (int q = 0; q < 4; q++) acc[mi][ni][q] = 0.f;

    load_chunk(0, 0);

    for (int c = 0; c < NCHUNK; ++c) {
        const int s = c & 1;
        if (c + 1 < NCHUNK) {
            load_chunk(c + 1, s ^ 1);
            asm volatile("cp.async.wait_group 1;" ::: "memory");
        } else {
            asm volatile("cp.async.wait_group 0;" ::: "memory");
        }
        __syncthreads();

        const uint32_t abase = sAu[s] + aoff;
        const uint32_t bbase = sBu[s] + boff;
#pragma unroll
        for (int k16 = 0; k16 < 4; k16++) {
            uint32_t af[4][4], bq[2][4];
#pragma unroll
            for (int mi = 0; mi < 4; mi++)
                ldsm_x4(af[mi], abase + mi * AMI + k16 * 32);
#pragma unroll
            for (int nip = 0; nip < 2; nip++)
                ldsm_x4(bq[nip], bbase + nip * BNI + k16 * 32);
#pragma unroll
            for (int mi = 0; mi < 4; mi++)
#pragma unroll
                for (int ni = 0; ni < 4; ni++)
                    mma_f16_16x8x16(acc[mi][ni], af[mi], &bq[ni >> 1][(ni & 1) * 2]);
        }
        __syncthreads();
    }

#pragma unroll
    for (int mi = 0; mi < 4; mi++) {
        const int r0 = bm + wm + mi * 16 + gid;
#pragma unroll
        for (int ni = 0; ni < 4; ni++) {
            const int c0 = bn + wn + ni * 8 + tg * 2;
            if (out_half) {
                __half* Ch = (__half*)Cv;
                *reinterpret_cast<__half2*>(&Ch[(size_t)r0 * N + c0]) =
                    __floats2half2_rn(acc[mi][ni][0], acc[mi][ni][1]);
                *reinterpret_cast<__half2*>(&Ch[(size_t)(r0 + 8) * N + c0]) =
                    __floats2half2_rn(acc[mi][ni][2], acc[mi][ni][3]);
            } else {
                float* Cf = (float*)Cv;
                *reinterpret_cast<float2*>(&Cf[(size_t)r0 * N + c0]) =
                    make_float2(acc[mi][ni][0], acc[mi][ni][1]);
                *reinterpret_cast<float2*>(&Cf[(size_t)(r0 + 8) * N + c0]) =
                    make_float2(acc[mi][ni][2], acc[mi][ni][3]);
            }
        }
    }
}

// ---------------------------------------------------------------------------
// FA2-style attention with warp-local windowed fragments: each warp's 16 rows
// see at most 144 valid keys -> compute 18 (not 24) score frags and 9 (not 12)
// PV k-steps. Skipped fragments are fully masked => bit-identical output.
// ---------------------------------------------------------------------------
__global__ void __launch_bounds__(ATHR, 3) attn_mma(const __half* __restrict__ qkv,
                                                    __half* __restrict__ att) {
    const int q0 = blockIdx.x * QT;
    const int h  = blockIdx.y;
    const int b  = blockIdx.z;
    const int tid = threadIdx.x;
    const int wid = tid >> 5, lane = tid & 31;
    const int gid = lane >> 2, tg = lane & 3;
    const int mrow = wid * 16;

    extern __shared__ __half smh[];
    __half* sQ = smh;
    __half* sK = sQ + QT  * SQH;
    __half* sV = sK + NKM * SQH;

    const int kstart = max(0, q0 - WIN);
    const int nk     = q0 + QT - kstart;
    const int hq     = h * HD;
    const size_t rowbase = (size_t)(b * TT) * (3 * DD);

    for (int idx = tid; idx < QT * (HD / 8); idx += ATHR) {
        int q = idx >> 3, d8 = (idx & 7) * 8;
        uint4 v = *reinterpret_cast<const uint4*>(
            &qkv[rowbase + (size_t)(q0 + q) * (3 * DD) + hq + d8]);
        *reinterpret_cast<uint4*>(&sQ[q * SQH + d8]) = v;
    }
    for (int idx = tid; idx < nk * (HD / 8); idx += ATHR) {
        int kk = idx >> 3, d8 = (idx & 7) * 8;
        uint4 v = *reinterpret_cast<const uint4*>(
            &qkv[rowbase + (size_t)(kstart + kk) * (3 * DD) + DD + hq + d8]);
        *reinterpret_cast<uint4*>(&sK[kk * SQH + d8]) = v;
        uint4 w = *reinterpret_cast<const uint4*>(
            &qkv[rowbase + (size_t)(kstart + kk) * (3 * DD) + 2 * DD + hq + d8]);
        *reinterpret_cast<uint4*>(&sV[kk * SQH + d8]) = w;
    }
    // Zero K/V rows [nk, NKM): skipping covers only frags fully outside the
    // window; partially-valid frags near nk still touch these rows.
    for (int idx = nk * (HD / 8) + tid; idx < NKM * (HD / 8); idx += ATHR) {
        int kk = idx >> 3, d8 = (idx & 7) * 8;
        *reinterpret_cast<uint4*>(&sV[kk * SQH + d8]) = make_uint4(0u, 0u, 0u, 0u);
        *reinterpret_cast<uint4*>(&sK[kk * SQH + d8]) = make_uint4(0u, 0u, 0u, 0u);
    }
    __syncthreads();

    const uint32_t uQ = smem_u32(sQ);
    const uint32_t uK = smem_u32(sK);
    const uint32_t uV = smem_u32(sV);

    // Warp-local valid-key window: rel columns [8*nlo, 8*nlo + 144).
    // nlo is even (mrow multiple of 16, kstart = 0 or q0-128).
    const int nlo  = max(0, q0 + mrow - WIN - kstart) >> 3;
    const int col0 = nlo * 8;

    // ---- QK^T: 18 n-frags x 4 k16 steps ----
    float accS[18][4];
#pragma unroll
    for (int t = 0; t < 18; t++)
#pragma unroll
        for (int q = 0; q < 4; q++) accS[t][q] = 0.f;

    {
        const uint32_t aoff = uQ + (uint32_t)((mrow + (lane & 7) + ((lane >> 3) & 1) * 8) * SQH
                                              + (lane >> 4) * 8) * 2u;
        const uint32_t boff = uK + (uint32_t)((col0 + (lane & 7) + ((lane >> 4) & 1) * 8) * SQH
                                              + ((lane >> 3) & 1) * 8) * 2u;
#pragma unroll
        for (int k16 = 0; k16 < 4; k16++) {
            uint32_t af[4];
            ldsm_x4(af, aoff + k16 * 32);
#pragma unroll
            for (int nip = 0; nip < 9; nip++) {
                uint32_t bq[4];
                ldsm_x4(bq, boff + nip * (16 * SQH * 2) + k16 * 32);
                mma_f16_16x8x16(accS[nip * 2],     af, &bq[0]);
                mma_f16_16x8x16(accS[nip * 2 + 1], af, &bq[2]);
            }
        }
    }

    // ---- mask + scale ----
    const int i0 = q0 + mrow + gid, i1 = i0 + 8;
    const float scale = 0.125f;
#pragma unroll
    for (int t = 0; t < 18; t++) {
        const int j0 = kstart + col0 + t * 8 + 2 * tg, j1 = j0 + 1;
        accS[t][0] = (j0 <= i0 && j0 >= i0 - WIN) ? accS[t][0] * scale : -1e30f;
        accS[t][1] = (j1 <= i0 && j1 >= i0 - WIN) ? accS[t][1] * scale : -1e30f;
        accS[t][2] = (j0 <= i1 && j0 >= i1 - WIN) ? accS[t][2] * scale : -1e30f;
        accS[t][3] = (j1 <= i1 && j1 >= i1 - WIN) ? accS[t][3] * scale : -1e30f;
    }

    // ---- row max ----
    float m0 = -1e30f, m1 = -1e30f;
#pragma unroll
    for (int t = 0; t < 18; t++) {
        m0 = fmaxf(m0, fmaxf(accS[t][0], accS[t][1]));
        m1 = fmaxf(m1, fmaxf(accS[t][2], accS[t][3]));
    }
    m0 = fmaxf(m0, __shfl_xor_sync(0xffffffffu, m0, 1));
    m0 = fmaxf(m0, __shfl_xor_sync(0xffffffffu, m0, 2));
    m1 = fmaxf(m1, __shfl_xor_sync(0xffffffffu, m1, 1));
    m1 = fmaxf(m1, __shfl_xor_sync(0xffffffffu, m1, 2));

    // ---- exp + row sum ----
    float s0 = 0.f, s1 = 0.f;
#pragma unroll
    for (int t = 0; t < 18; t++) {
        accS[t][0] = __expf(accS[t][0] - m0);
        accS[t][1] = __expf(accS[t][1] - m0);
        accS[t][2] = __expf(accS[t][2] - m1);
        accS[t][3] = __expf(accS[t][3] - m1);
        s0 += accS[t][0] + accS[t][1];
        s1 += accS[t][2] + accS[t][3];
    }
    s0 += __shfl_xor_sync(0xffffffffu, s0, 1);
    s0 += __shfl_xor_sync(0xffffffffu, s0, 2);
    s1 += __shfl_xor_sync(0xffffffffu, s1, 1);
    s1 += __shfl_xor_sync(0xffffffffu, s1, 2);
    const float inv0 = 1.f / s0, inv1 = 1.f / s1;

    // ---- pack P ----
    uint32_t pf[18], pg[18];
#pragma unroll
    for (int t = 0; t < 18; t++) {
        pf[t] = pack_h2(accS[t][0] * inv0, accS[t][1] * inv0);
        pg[t] = pack_h2(accS[t][2] * inv1, accS[t][3] * inv1);
    }

    // ---- PV: 9 k16 steps starting at k16b = nlo/2 ----
    float accO[8][4];
#pragma unroll
    for (int ni = 0; ni < 8; ni++)
#pragma unroll
        for (int q = 0; q < 4; q++) accO[ni][q] = 0.f;

    {
        const uint32_t vbase = uV + (uint32_t)((col0 + (lane & 7) + ((lane >> 3) & 1) * 8) * SQH
                                               + ((lane >> 4) & 1) * 8) * 2u;
#pragma unroll
        for (int t = 0; t < 9; t++) {
            uint32_t af[4] = { pf[2 * t], pg[2 * t], pf[2 * t + 1], pg[2 * t + 1] };
#pragma unroll
            for (int dp = 0; dp < 4; dp++) {
                uint32_t bq[4];
                ldsm_x4_t(bq, vbase + (uint32_t)(t * 16 * SQH + dp * 16) * 2u);
                mma_f16_16x8x16(accO[dp * 2],     af, &bq[0]);
                mma_f16_16x8x16(accO[dp * 2 + 1], af, &bq[2]);
            }
        }
    }

#pragma unroll
    for (int ni = 0; ni < 8; ni++) {
        const int dc = ni * 8 + 2 * tg;
        const int r  = mrow + gid;
        *reinterpret_cast<__half2*>(&att[(size_t)(b * TT + q0 + r) * DD + hq + dc]) =
            __floats2half2_rn(accO[ni][0], accO[ni][1]);
        *reinterpret_cast<__half2*>(&att[(size_t)(b * TT + q0 + r + 8) * DD + hq + dc]) =
            __floats2half2_rn(accO[ni][2], accO[ni][3]);
    }
}

// ---------------------------------------------------------------------------
extern "C" void kernel_launch(void* const* d_in, const int* in_sizes, int n_in,
                              void* d_out, int out_size) {
    const float* x    = (const float*)d_in[0];
    const float* Wqkv = (const float*)d_in[1];
    const float* Wout = (const float*)d_in[2];
    float* out = (float*)d_out;

    __half *x16, *qkv, *att, *wqkvT, *woutT;
    cudaGetSymbolAddress((void**)&x16, g_x16);
    cudaGetSymbolAddress((void**)&qkv, g_qkv);
    cudaGetSymbolAddress((void**)&att, g_att);
    cudaGetSymbolAddress((void**)&wqkvT, g_wqkvT);
    cudaGetSymbolAddress((void**)&woutT, g_woutT);

    cudaFuncSetAttribute(attn_mma, cudaFuncAttributeMaxDynamicSharedMemorySize, ATT_SMEM);
    cudaFuncSetAttribute(gemm_f16, cudaFuncAttributeMaxDynamicSharedMemorySize, GEMM_SMEM);

    const int M = BB * TT;   // 8192

    // 0) fused preprocessing
    pre_k<<<PRE_BLKS, 256>>>(x, x16, Wqkv, wqkvT, Wout, woutT);

    // 1) QKV projection: grid (18, 64), 128x128 tile
    gemm_f16<<<dim3(3 * DD / NT, M / MT), GEMM_THREADS, GEMM_SMEM>>>(x16, wqkvT, qkv, 3 * DD, 1);

    // 2) attention (windowed fragments)
    attn_mma<<<dim3(TT / QT, HH, BB), ATHR, ATT_SMEM>>>(qkv, att);

    // 3) output projection: grid (6, 64)
    gemm_f16<<<dim3(DD / NT, M / MT), GEMM_THREADS, GEMM_SMEM>>>(att, woutT, out, DD, 0);
}